// round 11
// baseline (speedup 1.0000x reference)
#include <cuda_runtime.h>

// ---------------- problem constants ----------------
#define BATCH 1024
#define C0_ 512
#define C1_ 1024
#define K0_ 100
#define K1_ 50
#define KP0 128
#define KP1 64
#define ROWS0 (BATCH*C0_)   // 524288
#define ROWS1 (BATCH*C1_)   // 1048576

#define MB 8
#define NT (BATCH/MB)       // 128 tiles per head
#define PITCH0 132          // KP0+4, float4-aligned
#define PITCH1 66           // KP1+2, float2-aligned
#define CC0 32
#define CC1 64

// ---------------- scratch ----------------
__device__ float    g_pooled0[ROWS0];
__device__ float    g_pooled1[ROWS1];
__device__ float    g_accum[4] = {0.f, 0.f, 0.f, 0.f};
__device__ unsigned g_done = 0u;

// ---------------- fused pooling ----------------
// pool0 blocks: 8 warps x 2 rows each (MLP 4). pool1 blocks: 128-row smem tiles.
#define NB0 (ROWS0/16)          // 32768
#define P1_RPB 128
#define P1_FLT (P1_RPB*49)      // 6272
#define P1_VEC (P1_FLT/4)       // 1568
#define NB1 (ROWS1/P1_RPB)      // 8192

__global__ void __launch_bounds__(256)
pool_kernel(const float* __restrict__ feat0, const float* __restrict__ feat1) {
    __shared__ float sf[P1_FLT];
    if (blockIdx.x == 0 && threadIdx.x < 5) {
        if (threadIdx.x < 4) g_accum[threadIdx.x] = 0.0f;
        else g_done = 0u;
    }
    if (blockIdx.x < NB0) {
        const unsigned w    = threadIdx.x >> 5;
        const unsigned lane = threadIdx.x & 31u;
        const unsigned row  = blockIdx.x * 16u + w * 2u;   // 2 rows per warp
        const float4* src = reinterpret_cast<const float4*>(feat0) + (size_t)row * 49;
        // 4 independent loads in flight
        float4 a0 = __ldcs(src + lane);
        float4 a1 = __ldcs(src + 49 + lane);
        float x0 = (a0.x + a0.y) + (a0.z + a0.w);
        float x1 = (a1.x + a1.y) + (a1.z + a1.w);
        if (lane < 17u) {
            float4 c0 = __ldcs(src + 32 + lane);
            float4 c1 = __ldcs(src + 81 + lane);
            x0 += (c0.x + c0.y) + (c0.z + c0.w);
            x1 += (c1.x + c1.y) + (c1.z + c1.w);
        }
        #pragma unroll
        for (int o = 16; o; o >>= 1) {
            x0 += __shfl_xor_sync(0xffffffffu, x0, o);
            x1 += __shfl_xor_sync(0xffffffffu, x1, o);
        }
        if (lane == 0u) {
            g_pooled0[row]     = x0 * (1.0f / 196.0f);
            g_pooled0[row + 1] = x1 * (1.0f / 196.0f);
        }
    } else {
        const unsigned blk = blockIdx.x - NB0;
        const float4* src = reinterpret_cast<const float4*>(feat1) + (size_t)blk * P1_VEC;
        float4* dst = reinterpret_cast<float4*>(sf);
        #pragma unroll 4
        for (int i = threadIdx.x; i < P1_VEC; i += 256)
            dst[i] = __ldcs(src + i);
        __syncthreads();
        const int t = threadIdx.x;
        if (t < P1_RPB) {
            const float* r = sf + t * 49;
            float s0 = 0.f, s1 = 0.f, s2 = 0.f, s3 = 0.f;
            #pragma unroll
            for (int e = 0; e < 48; e += 4) {
                s0 += r[e]; s1 += r[e+1]; s2 += r[e+2]; s3 += r[e+3];
            }
            g_pooled1[(size_t)blk * P1_RPB + t] =
                ((s0 + s1) + (s2 + s3) + r[48]) * (1.0f / 49.0f);
        }
    }
}

// ---------------- head tile v4: warp-per-row, vectorized, pipelined --------
// 256 thr = 8 warps(=rows) x 32 k-groups. sp reads are warp broadcasts.
// h0: sp 16384 + swt 2*32*132*4=33792 + slg 4224 = 54400
// h1: sp 32768 + swt 2*64*66*4=33792  + slg 2112 = 68672
#define HEAD_SMEM 68672

template<int C, int K, int KPAD, int TK, int CCH, int PITCH, int AOFF>
__device__ __forceinline__ void head_tile(
    const float* __restrict__ pooled,
    const float* __restrict__ W, const float* __restrict__ bias,
    const int* __restrict__ lut, const float* __restrict__ cw,
    const int* __restrict__ target, int m0, char* sraw)
{
    float* sp = reinterpret_cast<float*>(sraw);                          // [MB*C]
    float (*swt)[CCH][PITCH] =
        reinterpret_cast<float(*)[CCH][PITCH]>(sraw + 4*MB*C);
    float (*slg)[PITCH] =
        reinterpret_cast<float(*)[PITCH]>(sraw + 4*(MB*C + 2*CCH*PITCH));

    const int tid  = threadIdx.x;
    const int ktg  = tid & 31;          // k-group (owns TK consecutive k)
    const int bt   = tid >> 5;          // warp id = batch row
    constexpr int NLD = KPAD * CCH / 256;   // 16 both heads

    // stage pooled tile once (contiguous)
    {
        const float4* src = reinterpret_cast<const float4*>(pooled + (size_t)m0 * C);
        float4* dst = reinterpret_cast<float4*>(sp);
        #pragma unroll
        for (int i = tid; i < MB * C / 4; i += 256) dst[i] = src[i];
    }

    float ld[NLD];
    // prologue: W tile 0 (coalesced along c; transposed store)
    #pragma unroll
    for (int j = 0; j < NLD; j++) {
        const int idx = tid + j * 256;
        const int c = idx & (CCH - 1), k = idx / CCH;
        ld[j] = (k < K) ? W[(size_t)k * C + c] : 0.0f;
    }
    #pragma unroll
    for (int j = 0; j < NLD; j++) {
        const int idx = tid + j * 256;
        swt[0][idx & (CCH - 1)][idx / CCH] = ld[j];
    }
    __syncthreads();

    float acc[TK];
    #pragma unroll
    for (int t = 0; t < TK; t++) acc[t] = 0.0f;

    constexpr int NCH = C / CCH;
    #pragma unroll 1
    for (int ch = 0; ch < NCH; ch++) {
        if (ch + 1 < NCH) {
            const int c0 = (ch + 1) * CCH;
            #pragma unroll
            for (int j = 0; j < NLD; j++) {
                const int idx = tid + j * 256;
                const int c = idx & (CCH - 1), k = idx / CCH;
                ld[j] = (k < K) ? W[(size_t)k * C + c0 + c] : 0.0f;
            }
        }
        const float* sr = sp + bt * C + ch * CCH;
        const float (*wt)[PITCH] = swt[ch & 1];
        #pragma unroll
        for (int c4 = 0; c4 < CCH / 4; c4++) {
            float4 p = *reinterpret_cast<const float4*>(sr + c4 * 4);   // broadcast
            const float pe[4] = {p.x, p.y, p.z, p.w};
            #pragma unroll
            for (int cc = 0; cc < 4; cc++) {
                const int c = c4 * 4 + cc;
                if (TK == 4) {
                    float4 wv = *reinterpret_cast<const float4*>(&wt[c][ktg * 4]);
                    acc[0] = fmaf(pe[cc], wv.x, acc[0]);
                    acc[1] = fmaf(pe[cc], wv.y, acc[1]);
                    acc[2] = fmaf(pe[cc], wv.z, acc[2]);
                    acc[3] = fmaf(pe[cc], wv.w, acc[3]);
                } else {
                    float2 wv = *reinterpret_cast<const float2*>(&wt[c][ktg * 2]);
                    acc[0] = fmaf(pe[cc], wv.x, acc[0]);
                    acc[1] = fmaf(pe[cc], wv.y, acc[1]);
                }
            }
        }
        if (ch + 1 < NCH) {
            #pragma unroll
            for (int j = 0; j < NLD; j++) {
                const int idx = tid + j * 256;
                swt[(ch + 1) & 1][idx & (CCH - 1)][idx / CCH] = ld[j];
            }
        }
        __syncthreads();
    }

    // logits -> smem
    #pragma unroll
    for (int t = 0; t < TK; t++) {
        const int k = ktg * TK + t;
        slg[bt][k] = acc[t] + ((k < K) ? bias[k] : 0.0f);
    }
    __syncthreads();

    // softmax-CE: warp per row
    const int lane = tid & 31;
    {
        float m = -3.4e38f;
        for (int k = lane; k < K; k += 32) m = fmaxf(m, slg[bt][k]);
        #pragma unroll
        for (int o = 16; o; o >>= 1) m = fmaxf(m, __shfl_xor_sync(0xffffffffu, m, o));
        float s = 0.0f;
        for (int k = lane; k < K; k += 32) s += __expf(slg[bt][k] - m);
        #pragma unroll
        for (int o = 16; o; o >>= 1) s += __shfl_xor_sync(0xffffffffu, s, o);
        if (lane == 0) {
            const int t = lut[target[m0 + bt]];
            const float nll = m + __logf(s) - slg[bt][t];
            const float wt  = cw[t];
            atomicAdd(&g_accum[AOFF],     wt * nll);
            atomicAdd(&g_accum[AOFF + 1], wt);
        }
    }
    __syncthreads();
}

// heads + in-kernel finalize
__global__ void __launch_bounds__(256)
heads_kernel(const float* __restrict__ W0, const float* __restrict__ b0v,
             const int* __restrict__ lut0, const float* __restrict__ cw0,
             const float* __restrict__ W1, const float* __restrict__ b1v,
             const int* __restrict__ lut1, const float* __restrict__ cw1,
             const int* __restrict__ target, float* __restrict__ out)
{
    extern __shared__ __align__(16) char sraw[];
    const unsigned nblocks = 2u * NT;   // 256
    if (blockIdx.x < NT)
        head_tile<C0_, K0_, KP0, 4, CC0, PITCH0, 0>(
            g_pooled0, W0, b0v, lut0, cw0, target, blockIdx.x * MB, sraw);
    else
        head_tile<C1_, K1_, KP1, 2, CC1, PITCH1, 2>(
            g_pooled1, W1, b1v, lut1, cw1, target,
            (blockIdx.x - NT) * MB, sraw);

    if (threadIdx.x == 0) {
        __threadfence();
        const unsigned arrived = atomicAdd(&g_done, 1u);
        if (arrived == nblocks - 1u) {
            const float n0 = atomicAdd(&g_accum[0], 0.0f);
            const float d0 = atomicAdd(&g_accum[1], 0.0f);
            const float n1 = atomicAdd(&g_accum[2], 0.0f);
            const float d1 = atomicAdd(&g_accum[3], 0.0f);
            out[0] = n0 / d0 + n1 / d1;
            #pragma unroll
            for (int i = 0; i < 4; i++) atomicExch(&g_accum[i], 0.0f);
            __threadfence();
            atomicExch(&g_done, 0u);
        }
    }
}

// ---------------- launch ----------------
extern "C" void kernel_launch(void* const* d_in, const int* in_sizes, int n_in,
                              void* d_out, int out_size) {
    (void)in_sizes; (void)n_in; (void)out_size;
    const float* feat0  = (const float*)d_in[0];
    const float* feat1  = (const float*)d_in[1];
    const float* W0     = (const float*)d_in[2];
    const float* b0v    = (const float*)d_in[3];
    const float* W1     = (const float*)d_in[4];
    const float* b1v    = (const float*)d_in[5];
    const int*   lut0   = (const int*)d_in[6];
    const int*   lut1   = (const int*)d_in[7];
    const float* cw0    = (const float*)d_in[8];
    const float* cw1    = (const float*)d_in[9];
    const int*   target = (const int*)d_in[10];
    float* out = (float*)d_out;

    cudaFuncSetAttribute(heads_kernel,
                         cudaFuncAttributeMaxDynamicSharedMemorySize, HEAD_SMEM);

    pool_kernel<<<NB0 + NB1, 256>>>(feat0, feat1);
    heads_kernel<<<2 * NT, 256, HEAD_SMEM>>>(
        W0, b0v, lut0, cw0, W1, b1v, lut1, cw1, target, out);
}